// round 6
// baseline (speedup 1.0000x reference)
#include <cuda_runtime.h>

#define Nn 32
#define Cc 512
#define Hh 64
#define Ww 64
#define CBn 32          // bottleneck channels C/R
#define Sp (Hh*Ww)      // 4096 spatial per channel
#define EPSv 1e-5f
#define GRP 4           // 4 * 8MB = 32MB per group; 3 in flight = 96MB < 126MB L2
#define NSTREAMS 3
#define CG 32           // channels per add-block
#define NCG (Cc/CG)     // 16 channel-groups

// Scratch (allocation-free rule: __device__ globals). Indexed by global n ->
// disjoint across concurrently-running groups.
__device__ float g_logit[Nn * Sp];     // raw logits (softmax applied by consumers)
__device__ float g_ctx[Nn * Cc];       // pooled context

// ---------------------------------------------------------------------------
// K1: logits[n,h,w] = sum_c x[n,c,h,w] * wk_w[c] + wk_b
// block = (n,h) row; 256 threads = 16 w-float4 groups x 16 c-chunks of 32
// ---------------------------------------------------------------------------
__global__ void __launch_bounds__(256, 6)
k_logits(const float* __restrict__ x,
         const float* __restrict__ wk_w,
         const float* __restrict__ wk_b, int n0) {
    int n = n0 + (blockIdx.x >> 6);   // / Hh
    int h = blockIdx.x & 63;          // % Hh
    int tid = threadIdx.x;            // 0..255
    int wq = tid & 15;                // float4 index over w (w = wq*4)
    int cc = tid >> 4;                // c-chunk 0..15 (32 channels each)

    const float4* xp = (const float4*)(x + (((size_t)(n * Cc + cc * 32)) * Hh + h) * Ww) + wq;
    const size_t cstride4 = Sp / 4;   // float4 stride between channels = 1024

    float4 acc = make_float4(0.f, 0.f, 0.f, 0.f);
#pragma unroll 8
    for (int i = 0; i < 32; i++) {
        float wv = __ldg(&wk_w[cc * 32 + i]);
        float4 v = __ldg(xp + (size_t)i * cstride4);
        acc.x += v.x * wv; acc.y += v.y * wv;
        acc.z += v.z * wv; acc.w += v.w * wv;
    }

    __shared__ float sred[16][Ww];
    sred[cc][wq * 4 + 0] = acc.x;
    sred[cc][wq * 4 + 1] = acc.y;
    sred[cc][wq * 4 + 2] = acc.z;
    sred[cc][wq * 4 + 3] = acc.w;
    __syncthreads();

    if (tid < Ww) {
        float s = 0.f;
#pragma unroll
        for (int k = 0; k < 16; k++) s += sred[k][tid];
        g_logit[((size_t)n * Hh + h) * Ww + tid] = s + __ldg(&wk_b[0]);
    }
}

// ---------------------------------------------------------------------------
// K2: ctx[n,c] = sum_{h,w} x[n,c,h,w] * softmax_H(logit)[n,h,w]
// block per (n,c); 128 threads. Softmax is computed per block from the L2-hot
// 16KB logits tile: 64 threads compute per-w (max, 1/sum), then attn values
// are reconstructed on the fly during the dot loop (exp + scale, MUFU-hidden).
// ---------------------------------------------------------------------------
__global__ void k_ctx(const float* __restrict__ x, int n0) {
    int n = n0 + (blockIdx.x >> 9);   // / Cc
    int c = blockIdx.x & 511;         // % Cc
    int tid = threadIdx.x;            // 0..127

    __shared__ float slog[Sp];        // 16KB logits tile
    __shared__ float smax[Ww];
    __shared__ float sinv[Ww];

    const float4* lp = (const float4*)(g_logit + (size_t)n * Sp);
#pragma unroll
    for (int i = 0; i < 8; i++)
        ((float4*)slog)[tid + i * 128] = __ldg(lp + tid + i * 128);
    __syncthreads();

    if (tid < Ww) {
        int w = tid;
        float m = -1e30f;
#pragma unroll
        for (int h = 0; h < Hh; h++) m = fmaxf(m, slog[h * Ww + w]);
        float sum = 0.f;
#pragma unroll
        for (int h = 0; h < Hh; h++) sum += __expf(slog[h * Ww + w] - m);
        smax[w] = m;
        sinv[w] = 1.f / sum;
    }
    __syncthreads();

    const float4* xp = (const float4*)(x + ((size_t)n * Cc + c) * Sp);
    float acc = 0.f;
#pragma unroll
    for (int i = 0; i < 8; i++) {
        int f = tid + i * 128;        // float4 index; scalars 4f..4f+3
        float4 xv = __ldg(xp + f);
        int idx = f * 4;
        int w0 = idx & 63;            // 4 consecutive w (same h: 64%4==0)
        float a0 = __expf(slog[idx + 0] - smax[w0 + 0]) * sinv[w0 + 0];
        float a1 = __expf(slog[idx + 1] - smax[w0 + 1]) * sinv[w0 + 1];
        float a2 = __expf(slog[idx + 2] - smax[w0 + 2]) * sinv[w0 + 2];
        float a3 = __expf(slog[idx + 3] - smax[w0 + 3]) * sinv[w0 + 3];
        acc += xv.x * a0 + xv.y * a1 + xv.z * a2 + xv.w * a3;
    }

    __shared__ float s[128];
    s[tid] = acc;
    __syncthreads();
    if (tid < 64) s[tid] += s[tid + 64];
    __syncthreads();
    if (tid < 32) {
        float v = s[tid] + s[tid + 32];
#pragma unroll
        for (int o = 16; o; o >>= 1) v += __shfl_xor_sync(0xffffffffu, v, o);
        if (tid == 0) g_ctx[(size_t)n * Cc + c] = v;
    }
}

// ---------------------------------------------------------------------------
// K3: add + inline MLP. Block per (n, channel-group of CG=32). 256 threads.
// Prologue (redundant per block, L2-hot weights):
//   v_j = dot(ctx[n,:], wv1[j,:])  -- 8 warps x 4 j
//   LayerNorm+ReLU (warp 0)
//   delta[c] for this block's 32 channels (threads 0..31)
// Then stream: out = x + delta[c] over 32 x 4096 floats.
// ---------------------------------------------------------------------------
__global__ void __launch_bounds__(256)
k_addmlp(const float* __restrict__ x, float* __restrict__ out,
         const float* __restrict__ wv1,
         const float* __restrict__ ln_g,
         const float* __restrict__ ln_b,
         const float* __restrict__ wv2, int n0) {
    int n = n0 + (blockIdx.x >> 4);   // / NCG
    int cg = blockIdx.x & 15;         // % NCG
    int tid = threadIdx.x;            // 0..255
    int wid = tid >> 5;               // 0..7
    int lane = tid & 31;

    __shared__ float sctx[Cc];
    __shared__ float sv[CBn];
    __shared__ float sdelta[CG];

    if (tid < Cc / 4)
        ((float4*)sctx)[tid] = __ldg((const float4*)(g_ctx + (size_t)n * Cc) + tid);
    __syncthreads();

    // GEMV1: warp wid computes j = wid*4 + q, q=0..3
    float a0 = 0.f, a1 = 0.f, a2 = 0.f, a3 = 0.f;
    {
        const float* w1 = wv1 + (size_t)(wid * 4) * Cc;
#pragma unroll
        for (int k = 0; k < Cc / 32; k++) {
            int idx = lane + k * 32;
            float cx = sctx[idx];
            a0 += cx * __ldg(&w1[idx]);
            a1 += cx * __ldg(&w1[idx + Cc]);
            a2 += cx * __ldg(&w1[idx + 2 * Cc]);
            a3 += cx * __ldg(&w1[idx + 3 * Cc]);
        }
#pragma unroll
        for (int o = 16; o; o >>= 1) {
            a0 += __shfl_xor_sync(0xffffffffu, a0, o);
            a1 += __shfl_xor_sync(0xffffffffu, a1, o);
            a2 += __shfl_xor_sync(0xffffffffu, a2, o);
            a3 += __shfl_xor_sync(0xffffffffu, a3, o);
        }
        if (lane == 0) {
            sv[wid * 4 + 0] = a0;
            sv[wid * 4 + 1] = a1;
            sv[wid * 4 + 2] = a2;
            sv[wid * 4 + 3] = a3;
        }
    }
    __syncthreads();

    // LayerNorm + ReLU over 32 values (warp 0)
    if (wid == 0) {
        float v = sv[lane];
        float mu = v;
#pragma unroll
        for (int o = 16; o; o >>= 1) mu += __shfl_xor_sync(0xffffffffu, mu, o);
        mu *= (1.f / 32.f);
        float d = v - mu;
        float var = d * d;
#pragma unroll
        for (int o = 16; o; o >>= 1) var += __shfl_xor_sync(0xffffffffu, var, o);
        var *= (1.f / 32.f);
        v = d * rsqrtf(var + EPSv) * __ldg(&ln_g[lane]) + __ldg(&ln_b[lane]);
        sv[lane] = fmaxf(v, 0.f);
    }
    __syncthreads();

    // delta for this block's CG channels (threads 0..31, float4 weight loads)
    if (tid < CG) {
        int c = cg * CG + tid;
        const float4* w2 = (const float4*)(wv2 + (size_t)c * CBn);
        float s = 0.f;
#pragma unroll
        for (int q = 0; q < CBn / 4; q++) {
            float4 wv = __ldg(w2 + q);
            s += sv[q * 4 + 0] * wv.x + sv[q * 4 + 1] * wv.y
               + sv[q * 4 + 2] * wv.z + sv[q * 4 + 3] * wv.w;
        }
        sdelta[tid] = s;
    }
    __syncthreads();

    // Stream: CG channels x 4096 floats = 32768 float4 over 256 threads
    const float4* xp = (const float4*)(x + ((size_t)n * Cc + cg * CG) * Sp);
    float4* op = (float4*)(out + ((size_t)n * Cc + cg * CG) * Sp);
#pragma unroll 4
    for (int it = 0; it < (CG * Sp / 4) / 256; it++) {
        int f = it * 256 + tid;
        float4 v = __ldg(xp + f);
        float d = sdelta[f >> 10];    // 1024 float4 per channel
        op[f] = make_float4(v.x + d, v.y + d, v.z + d, v.w + d);
    }
}

// ---------------------------------------------------------------------------
extern "C" void kernel_launch(void* const* d_in, const int* in_sizes, int n_in,
                              void* d_out, int out_size) {
    const float* x    = (const float*)d_in[0];
    const float* wk_w = (const float*)d_in[1];
    const float* wk_b = (const float*)d_in[2];
    const float* wv1  = (const float*)d_in[3];
    const float* ln_g = (const float*)d_in[4];
    const float* ln_b = (const float*)d_in[5];
    const float* wv2  = (const float*)d_in[6];
    float* out = (float*)d_out;

    static cudaStream_t streams[NSTREAMS];
    static cudaEvent_t ev_root, ev_done[NSTREAMS];
    static bool res_init = false;
    if (!res_init) {
        for (int i = 0; i < NSTREAMS; i++) {
            cudaStreamCreateWithFlags(&streams[i], cudaStreamNonBlocking);
            cudaEventCreateWithFlags(&ev_done[i], cudaEventDisableTiming);
        }
        cudaEventCreateWithFlags(&ev_root, cudaEventDisableTiming);
        res_init = true;
    }

    // Fork the capture stream into side streams.
    cudaEventRecord(ev_root, 0);
    for (int i = 0; i < NSTREAMS; i++)
        cudaStreamWaitEvent(streams[i], ev_root, 0);

    for (int g = 0; g < Nn / GRP; g++) {
        int n0 = g * GRP;
        cudaStream_t st = streams[g % NSTREAMS];
        k_logits<<<GRP * Hh, 256, 0, st>>>(x, wk_w, wk_b, n0);
        k_ctx<<<GRP * Cc, 128, 0, st>>>(x, n0);
        k_addmlp<<<GRP * NCG, 256, 0, st>>>(x, out, wv1, ln_g, ln_b, wv2, n0);
    }

    for (int i = 0; i < NSTREAMS; i++) {
        cudaEventRecord(ev_done[i], streams[i]);
        cudaStreamWaitEvent(0, ev_done[i], 0);
    }
}

// round 7
// speedup vs baseline: 1.1061x; 1.1061x over previous
#include <cuda_runtime.h>

#define Nn 32
#define Cc 512
#define Hh 64
#define Ww 64
#define CBn 32          // bottleneck channels C/R
#define Sp (Hh*Ww)      // 4096 spatial per channel
#define EPSv 1e-5f
#define GRP 4           // 4 * 8MB = 32MB per group; 3 in flight = 96MB < 126MB L2
#define NSTREAMS 3
#define CG 32           // channels per addmlp block
#define NCG (Cc/CG)     // 16 channel-groups

// Scratch (allocation-free rule: __device__ globals). Indexed by global n ->
// disjoint across concurrently-running groups.
__device__ float g_attn[Nn * Sp];      // logits -> attn (in place)
__device__ float g_ctx[Nn * Cc];       // pooled context

// ---------------------------------------------------------------------------
// K1: logits[n,h,w] = sum_c x[n,c,h,w] * wk_w[c] + wk_b
// block = (n,h) row; 256 threads = 16 w-float4 groups x 16 c-chunks of 32
// ---------------------------------------------------------------------------
__global__ void __launch_bounds__(256, 6)
k_logits(const float* __restrict__ x,
         const float* __restrict__ wk_w,
         const float* __restrict__ wk_b, int n0) {
    int n = n0 + (blockIdx.x >> 6);   // / Hh
    int h = blockIdx.x & 63;          // % Hh
    int tid = threadIdx.x;            // 0..255
    int wq = tid & 15;                // float4 index over w (w = wq*4)
    int cc = tid >> 4;                // c-chunk 0..15 (32 channels each)

    const float4* xp = (const float4*)(x + (((size_t)(n * Cc + cc * 32)) * Hh + h) * Ww) + wq;
    const size_t cstride4 = Sp / 4;   // float4 stride between channels = 1024

    float4 acc = make_float4(0.f, 0.f, 0.f, 0.f);
#pragma unroll 8
    for (int i = 0; i < 32; i++) {
        float wv = __ldg(&wk_w[cc * 32 + i]);
        float4 v = __ldg(xp + (size_t)i * cstride4);
        acc.x += v.x * wv; acc.y += v.y * wv;
        acc.z += v.z * wv; acc.w += v.w * wv;
    }

    __shared__ float sred[16][Ww];
    sred[cc][wq * 4 + 0] = acc.x;
    sred[cc][wq * 4 + 1] = acc.y;
    sred[cc][wq * 4 + 2] = acc.z;
    sred[cc][wq * 4 + 3] = acc.w;
    __syncthreads();

    if (tid < Ww) {
        float s = 0.f;
#pragma unroll
        for (int k = 0; k < 16; k++) s += sred[k][tid];
        g_attn[((size_t)n * Hh + h) * Ww + tid] = s + __ldg(&wk_b[0]);
    }
}

// ---------------------------------------------------------------------------
// K2: softmax over H (axis=1) for each (n, w), in place on g_attn. Tiny.
// ---------------------------------------------------------------------------
__global__ void k_softmax(int n0) {
    int n = n0 + blockIdx.x;
    int w = threadIdx.x;              // 0..63
    float* L = g_attn + (size_t)n * Sp;

    float vals[Hh];
    float m = -1e30f;
#pragma unroll
    for (int h = 0; h < Hh; h++) {
        vals[h] = L[h * Ww + w];
        m = fmaxf(m, vals[h]);
    }
    float sum = 0.f;
#pragma unroll
    for (int h = 0; h < Hh; h++) {
        vals[h] = __expf(vals[h] - m);
        sum += vals[h];
    }
    float inv = 1.f / sum;
#pragma unroll
    for (int h = 0; h < Hh; h++) L[h * Ww + w] = vals[h] * inv;
}

// ---------------------------------------------------------------------------
// K3: ctx[n,c] = sum_{h,w} x[n,c,h,w] * attn[n,h,w]   (x hits L2)
// block per (n,c); 128 threads reduce 4096 contiguous floats (float4).
// ---------------------------------------------------------------------------
__global__ void k_ctx(const float* __restrict__ x, int n0) {
    int n = n0 + (blockIdx.x >> 9);   // / Cc
    int c = blockIdx.x & 511;         // % Cc
    int tid = threadIdx.x;            // 0..127

    const float4* xp = (const float4*)(x + ((size_t)n * Cc + c) * Sp);
    const float4* ap = (const float4*)(g_attn + (size_t)n * Sp);

    float acc = 0.f;
#pragma unroll
    for (int i = 0; i < 8; i++) {
        float4 xv = __ldg(xp + tid + i * 128);
        float4 av = __ldg(ap + tid + i * 128);
        acc += xv.x * av.x + xv.y * av.y + xv.z * av.z + xv.w * av.w;
    }

    __shared__ float s[128];
    s[tid] = acc;
    __syncthreads();
    if (tid < 64) s[tid] += s[tid + 64];
    __syncthreads();
    if (tid < 32) {
        float v = s[tid] + s[tid + 32];
#pragma unroll
        for (int o = 16; o; o >>= 1) v += __shfl_xor_sync(0xffffffffu, v, o);
        if (tid == 0) g_ctx[(size_t)n * Cc + c] = v;
    }
}

// ---------------------------------------------------------------------------
// K4: add + inline MLP. Block per (n, channel-group of CG=32). 256 threads.
// Prologue (redundant per block, wv1 L2-hot, ~64KB):
//   v_j = dot(ctx[n,:], wv1[j,:])  -- 8 warps x 4 j
//   LayerNorm+ReLU (warp 0)
//   delta[c] for this block's 32 channels (threads 0..31)
// Then stream: out = x + delta[c] over 32 x 4096 floats.
// ---------------------------------------------------------------------------
__global__ void __launch_bounds__(256)
k_addmlp(const float* __restrict__ x, float* __restrict__ out,
         const float* __restrict__ wv1,
         const float* __restrict__ ln_g,
         const float* __restrict__ ln_b,
         const float* __restrict__ wv2, int n0) {
    int n = n0 + (blockIdx.x >> 4);   // / NCG
    int cg = blockIdx.x & 15;         // % NCG
    int tid = threadIdx.x;            // 0..255
    int wid = tid >> 5;               // 0..7
    int lane = tid & 31;

    __shared__ float sctx[Cc];
    __shared__ float sv[CBn];
    __shared__ float sdelta[CG];

    if (tid < Cc / 4)
        ((float4*)sctx)[tid] = __ldg((const float4*)(g_ctx + (size_t)n * Cc) + tid);
    __syncthreads();

    // GEMV1: warp wid computes j = wid*4 + q, q=0..3 (wv1 reads L2-hot)
    {
        float a0 = 0.f, a1 = 0.f, a2 = 0.f, a3 = 0.f;
        const float* w1 = wv1 + (size_t)(wid * 4) * Cc;
#pragma unroll
        for (int k = 0; k < Cc / 32; k++) {
            int idx = lane + k * 32;
            float cx = sctx[idx];
            a0 += cx * __ldg(&w1[idx]);
            a1 += cx * __ldg(&w1[idx + Cc]);
            a2 += cx * __ldg(&w1[idx + 2 * Cc]);
            a3 += cx * __ldg(&w1[idx + 3 * Cc]);
        }
#pragma unroll
        for (int o = 16; o; o >>= 1) {
            a0 += __shfl_xor_sync(0xffffffffu, a0, o);
            a1 += __shfl_xor_sync(0xffffffffu, a1, o);
            a2 += __shfl_xor_sync(0xffffffffu, a2, o);
            a3 += __shfl_xor_sync(0xffffffffu, a3, o);
        }
        if (lane == 0) {
            sv[wid * 4 + 0] = a0;
            sv[wid * 4 + 1] = a1;
            sv[wid * 4 + 2] = a2;
            sv[wid * 4 + 3] = a3;
        }
    }
    __syncthreads();

    // LayerNorm + ReLU over 32 values (warp 0)
    if (wid == 0) {
        float v = sv[lane];
        float mu = v;
#pragma unroll
        for (int o = 16; o; o >>= 1) mu += __shfl_xor_sync(0xffffffffu, mu, o);
        mu *= (1.f / 32.f);
        float d = v - mu;
        float var = d * d;
#pragma unroll
        for (int o = 16; o; o >>= 1) var += __shfl_xor_sync(0xffffffffu, var, o);
        var *= (1.f / 32.f);
        v = d * rsqrtf(var + EPSv) * __ldg(&ln_g[lane]) + __ldg(&ln_b[lane]);
        sv[lane] = fmaxf(v, 0.f);
    }
    __syncthreads();

    // delta for this block's CG channels (threads 0..31, float4 weight loads)
    if (tid < CG) {
        int c = cg * CG + tid;
        const float4* w2 = (const float4*)(wv2 + (size_t)c * CBn);
        float s = 0.f;
#pragma unroll
        for (int q = 0; q < CBn / 4; q++) {
            float4 wv = __ldg(w2 + q);
            s += sv[q * 4 + 0] * wv.x + sv[q * 4 + 1] * wv.y
               + sv[q * 4 + 2] * wv.z + sv[q * 4 + 3] * wv.w;
        }
        sdelta[tid] = s;
    }
    __syncthreads();

    // Stream: CG channels x 4096 floats = 32768 float4 over 256 threads
    const float4* xp = (const float4*)(x + ((size_t)n * Cc + cg * CG) * Sp);
    float4* op = (float4*)(out + ((size_t)n * Cc + cg * CG) * Sp);
#pragma unroll 4
    for (int it = 0; it < (CG * Sp / 4) / 256; it++) {
        int f = it * 256 + tid;
        float4 v = __ldg(xp + f);
        float d = sdelta[f >> 10];    // 1024 float4 per channel
        op[f] = make_float4(v.x + d, v.y + d, v.z + d, v.w + d);
    }
}

// ---------------------------------------------------------------------------
extern "C" void kernel_launch(void* const* d_in, const int* in_sizes, int n_in,
                              void* d_out, int out_size) {
    const float* x    = (const float*)d_in[0];
    const float* wk_w = (const float*)d_in[1];
    const float* wk_b = (const float*)d_in[2];
    const float* wv1  = (const float*)d_in[3];
    const float* ln_g = (const float*)d_in[4];
    const float* ln_b = (const float*)d_in[5];
    const float* wv2  = (const float*)d_in[6];
    float* out = (float*)d_out;

    static cudaStream_t streams[NSTREAMS];
    static cudaEvent_t ev_root, ev_done[NSTREAMS];
    static bool res_init = false;
    if (!res_init) {
        for (int i = 0; i < NSTREAMS; i++) {
            cudaStreamCreateWithFlags(&streams[i], cudaStreamNonBlocking);
            cudaEventCreateWithFlags(&ev_done[i], cudaEventDisableTiming);
        }
        cudaEventCreateWithFlags(&ev_root, cudaEventDisableTiming);
        res_init = true;
    }

    // Fork the capture stream into side streams.
    cudaEventRecord(ev_root, 0);
    for (int i = 0; i < NSTREAMS; i++)
        cudaStreamWaitEvent(streams[i], ev_root, 0);

    for (int g = 0; g < Nn / GRP; g++) {
        int n0 = g * GRP;
        cudaStream_t st = streams[g % NSTREAMS];
        k_logits<<<GRP * Hh, 256, 0, st>>>(x, wk_w, wk_b, n0);
        k_softmax<<<GRP, Ww, 0, st>>>(n0);
        k_ctx<<<GRP * Cc, 128, 0, st>>>(x, n0);
        k_addmlp<<<GRP * NCG, 256, 0, st>>>(x, out, wv1, ln_g, ln_b, wv2, n0);
    }

    for (int i = 0; i < NSTREAMS; i++) {
        cudaEventRecord(ev_done[i], streams[i]);
        cudaStreamWaitEvent(0, ev_done[i], 0);
    }
}

// round 8
// speedup vs baseline: 1.2414x; 1.1222x over previous
#include <cuda_runtime.h>

#define Nn 32
#define Cc 512
#define Hh 64
#define Ww 64
#define CBn 32          // bottleneck channels C/R
#define Sp (Hh*Ww)      // 4096 spatial per channel
#define EPSv 1e-5f
#define GRP 4           // 4 * 8MB = 32MB per group; 3 in flight = 96MB < 126MB L2
#define NSTREAMS 3

// Scratch (allocation-free rule: __device__ globals). Indexed by global n ->
// disjoint across concurrently-running groups.
__device__ float g_attn[Nn * Sp];      // logits -> attn (in place)
__device__ float g_ctx[Nn * Cc];       // pooled context
__device__ float g_v[Nn * CBn];        // post-LN/ReLU bottleneck vector

// ---------------------------------------------------------------------------
// K1: logits[n,h,w] = sum_c x[n,c,h,w] * wk_w[c] + wk_b
// block = (n,h) row; 256 threads = 16 w-float4 groups x 16 c-chunks of 32
// ---------------------------------------------------------------------------
__global__ void __launch_bounds__(256, 6)
k_logits(const float* __restrict__ x,
         const float* __restrict__ wk_w,
         const float* __restrict__ wk_b, int n0) {
    int n = n0 + (blockIdx.x >> 6);   // / Hh
    int h = blockIdx.x & 63;          // % Hh
    int tid = threadIdx.x;            // 0..255
    int wq = tid & 15;                // float4 index over w (w = wq*4)
    int cc = tid >> 4;                // c-chunk 0..15 (32 channels each)

    const float4* xp = (const float4*)(x + (((size_t)(n * Cc + cc * 32)) * Hh + h) * Ww) + wq;
    const size_t cstride4 = Sp / 4;   // float4 stride between channels = 1024

    float4 acc = make_float4(0.f, 0.f, 0.f, 0.f);
#pragma unroll 8
    for (int i = 0; i < 32; i++) {
        float wv = __ldg(&wk_w[cc * 32 + i]);
        float4 v = __ldg(xp + (size_t)i * cstride4);
        acc.x += v.x * wv; acc.y += v.y * wv;
        acc.z += v.z * wv; acc.w += v.w * wv;
    }

    __shared__ float sred[16][Ww];
    sred[cc][wq * 4 + 0] = acc.x;
    sred[cc][wq * 4 + 1] = acc.y;
    sred[cc][wq * 4 + 2] = acc.z;
    sred[cc][wq * 4 + 3] = acc.w;
    __syncthreads();

    if (tid < Ww) {
        float s = 0.f;
#pragma unroll
        for (int k = 0; k < 16; k++) s += sred[k][tid];
        g_attn[((size_t)n * Hh + h) * Ww + tid] = s + __ldg(&wk_b[0]);
    }
}

// ---------------------------------------------------------------------------
// K2: softmax over H (axis=1) per (n, w), in place. block per n, 256 threads:
// thread = (w, hq) with 4 h-chunks of 16 cooperating per column.
// ---------------------------------------------------------------------------
__global__ void k_softmax(int n0) {
    int n = n0 + blockIdx.x;
    int tid = threadIdx.x;            // 0..255
    int w = tid & 63;
    int hq = tid >> 6;                // 0..3
    float* L = g_attn + (size_t)n * Sp;

    __shared__ float sp[4][Ww];       // partials
    __shared__ float sfin[Ww];        // combined max / inv-sum

    float vals[16];
    float m = -1e30f;
#pragma unroll
    for (int i = 0; i < 16; i++) {
        vals[i] = L[(hq * 16 + i) * Ww + w];
        m = fmaxf(m, vals[i]);
    }
    sp[hq][w] = m;
    __syncthreads();
    if (hq == 0) sfin[w] = fmaxf(fmaxf(sp[0][w], sp[1][w]), fmaxf(sp[2][w], sp[3][w]));
    __syncthreads();
    float fm = sfin[w];

    float sum = 0.f;
#pragma unroll
    for (int i = 0; i < 16; i++) {
        vals[i] = __expf(vals[i] - fm);
        sum += vals[i];
    }
    sp[hq][w] = sum;
    __syncthreads();
    if (hq == 0) sfin[w] = 1.f / (sp[0][w] + sp[1][w] + sp[2][w] + sp[3][w]);
    __syncthreads();
    float inv = sfin[w];
#pragma unroll
    for (int i = 0; i < 16; i++) L[(hq * 16 + i) * Ww + w] = vals[i] * inv;
}

// ---------------------------------------------------------------------------
// K3: ctx[n,c] = sum_{h,w} x[n,c,h,w] * attn[n,h,w]   (x hits L2)
// block per (n,c); 128 threads reduce 4096 contiguous floats (float4).
// ---------------------------------------------------------------------------
__global__ void k_ctx(const float* __restrict__ x, int n0) {
    int n = n0 + (blockIdx.x >> 9);   // / Cc
    int c = blockIdx.x & 511;         // % Cc
    int tid = threadIdx.x;            // 0..127

    const float4* xp = (const float4*)(x + ((size_t)n * Cc + c) * Sp);
    const float4* ap = (const float4*)(g_attn + (size_t)n * Sp);

    float acc = 0.f;
#pragma unroll
    for (int i = 0; i < 8; i++) {
        float4 xv = __ldg(xp + tid + i * 128);
        float4 av = __ldg(ap + tid + i * 128);
        acc += xv.x * av.x + xv.y * av.y + xv.z * av.z + xv.w * av.w;
    }

    __shared__ float s[128];
    s[tid] = acc;
    __syncthreads();
    if (tid < 64) s[tid] += s[tid + 64];
    __syncthreads();
    if (tid < 32) {
        float v = s[tid] + s[tid + 32];
#pragma unroll
        for (int o = 16; o; o >>= 1) v += __shfl_xor_sync(0xffffffffu, v, o);
        if (tid == 0) g_ctx[(size_t)n * Cc + c] = v;
    }
}

// ---------------------------------------------------------------------------
// K4: bottleneck head only: v = ReLU(LN(ctx @ wv1^T)). grid=GRP, 256 threads
// (8 warps x 4 j). Weights 64KB, L2-hot after first group.
// ---------------------------------------------------------------------------
__global__ void k_bneck(const float* __restrict__ wv1,
                        const float* __restrict__ ln_g,
                        const float* __restrict__ ln_b, int n0) {
    int n = n0 + blockIdx.x;
    int tid = threadIdx.x;            // 0..255
    int wid = tid >> 5;               // 0..7
    int lane = tid & 31;

    __shared__ float sctx[Cc];
    __shared__ float sv[CBn];

    if (tid < Cc / 4)
        ((float4*)sctx)[tid] = __ldg((const float4*)(g_ctx + (size_t)n * Cc) + tid);
    __syncthreads();

    // warp wid computes j = wid*4 + q
    {
        float a0 = 0.f, a1 = 0.f, a2 = 0.f, a3 = 0.f;
        const float* w1 = wv1 + (size_t)(wid * 4) * Cc;
#pragma unroll
        for (int k = 0; k < Cc / 32; k++) {
            int idx = lane + k * 32;
            float cx = sctx[idx];
            a0 += cx * __ldg(&w1[idx]);
            a1 += cx * __ldg(&w1[idx + Cc]);
            a2 += cx * __ldg(&w1[idx + 2 * Cc]);
            a3 += cx * __ldg(&w1[idx + 3 * Cc]);
        }
#pragma unroll
        for (int o = 16; o; o >>= 1) {
            a0 += __shfl_xor_sync(0xffffffffu, a0, o);
            a1 += __shfl_xor_sync(0xffffffffu, a1, o);
            a2 += __shfl_xor_sync(0xffffffffu, a2, o);
            a3 += __shfl_xor_sync(0xffffffffu, a3, o);
        }
        if (lane == 0) {
            sv[wid * 4 + 0] = a0;
            sv[wid * 4 + 1] = a1;
            sv[wid * 4 + 2] = a2;
            sv[wid * 4 + 3] = a3;
        }
    }
    __syncthreads();

    if (wid == 0) {
        float v = sv[lane];
        float mu = v;
#pragma unroll
        for (int o = 16; o; o >>= 1) mu += __shfl_xor_sync(0xffffffffu, mu, o);
        mu *= (1.f / 32.f);
        float d = v - mu;
        float var = d * d;
#pragma unroll
        for (int o = 16; o; o >>= 1) var += __shfl_xor_sync(0xffffffffu, var, o);
        var *= (1.f / 32.f);
        v = d * rsqrtf(var + EPSv) * __ldg(&ln_g[lane]) + __ldg(&ln_b[lane]);
        g_v[(size_t)n * CBn + lane] = fmaxf(v, 0.f);
    }
}

// ---------------------------------------------------------------------------
// K5: out[n,c,:] = x[n,c,:] + dot(v[n,:], wv2[c,:]).  Block per (n,c), 256
// threads x 4 float4. Every thread redundantly computes the 32-FMA delta from
// L2-broadcast v + wv2 rows (256B) -- no sync, no extra hop.
// ---------------------------------------------------------------------------
__global__ void __launch_bounds__(256)
k_add(const float* __restrict__ x, float* __restrict__ out,
      const float* __restrict__ wv2, int n0) {
    int n = n0 + (blockIdx.x >> 9);   // / Cc
    int c = blockIdx.x & 511;         // % Cc
    int tid = threadIdx.x;            // 0..255

    // inline delta: d = dot(v[n,:], wv2[c,:])
    const float4* vp = (const float4*)(g_v + (size_t)n * CBn);
    const float4* w2 = (const float4*)(wv2 + (size_t)c * CBn);
    float d = 0.f;
#pragma unroll
    for (int q = 0; q < CBn / 4; q++) {
        float4 vv = __ldg(vp + q);
        float4 wv = __ldg(w2 + q);
        d += vv.x * wv.x + vv.y * wv.y + vv.z * wv.z + vv.w * wv.w;
    }

    const float4* xp = (const float4*)(x + ((size_t)n * Cc + c) * Sp);
    float4* op = (float4*)(out + ((size_t)n * Cc + c) * Sp);
#pragma unroll
    for (int it = 0; it < 4; it++) {
        int f = it * 256 + tid;       // 1024 float4 per channel
        float4 v = __ldg(xp + f);
        op[f] = make_float4(v.x + d, v.y + d, v.z + d, v.w + d);
    }
}

// ---------------------------------------------------------------------------
extern "C" void kernel_launch(void* const* d_in, const int* in_sizes, int n_in,
                              void* d_out, int out_size) {
    const float* x    = (const float*)d_in[0];
    const float* wk_w = (const float*)d_in[1];
    const float* wk_b = (const float*)d_in[2];
    const float* wv1  = (const float*)d_in[3];
    const float* ln_g = (const float*)d_in[4];
    const float* ln_b = (const float*)d_in[5];
    const float* wv2  = (const float*)d_in[6];
    float* out = (float*)d_out;

    static cudaStream_t streams[NSTREAMS];
    static cudaEvent_t ev_root, ev_done[NSTREAMS];
    static bool res_init = false;
    if (!res_init) {
        for (int i = 0; i < NSTREAMS; i++) {
            cudaStreamCreateWithFlags(&streams[i], cudaStreamNonBlocking);
            cudaEventCreateWithFlags(&ev_done[i], cudaEventDisableTiming);
        }
        cudaEventCreateWithFlags(&ev_root, cudaEventDisableTiming);
        res_init = true;
    }

    // Fork the capture stream into side streams.
    cudaEventRecord(ev_root, 0);
    for (int i = 0; i < NSTREAMS; i++)
        cudaStreamWaitEvent(streams[i], ev_root, 0);

    for (int g = 0; g < Nn / GRP; g++) {
        int n0 = g * GRP;
        cudaStream_t st = streams[g % NSTREAMS];
        k_logits<<<GRP * Hh, 256, 0, st>>>(x, wk_w, wk_b, n0);
        k_softmax<<<GRP, 256, 0, st>>>(n0);
        k_ctx<<<GRP * Cc, 128, 0, st>>>(x, n0);
        k_bneck<<<GRP, 256, 0, st>>>(wv1, ln_g, ln_b, n0);
        k_add<<<GRP * Cc, 256, 0, st>>>(x, out, wv2, n0);
    }

    for (int i = 0; i < NSTREAMS; i++) {
        cudaEventRecord(ev_done[i], streams[i]);
        cudaStreamWaitEvent(0, ev_done[i], 0);
    }
}

// round 10
// speedup vs baseline: 1.2706x; 1.0235x over previous
#include <cuda_runtime.h>

#define Nn 32
#define Cc 512
#define Hh 64
#define Ww 64
#define CBn 32          // bottleneck channels C/R
#define Sp (Hh*Ww)      // 4096 spatial per channel
#define EPSv 1e-5f
#define GRP 4           // 4 * 8MB = 32MB per group; 3 in flight = 96MB < 126MB L2
#define NSTREAMS 3

// Scratch (allocation-free rule: __device__ globals). Indexed by global n ->
// disjoint across concurrently-running groups.
__device__ float g_attn[Nn * Sp];      // logits -> attn (in place)
__device__ float g_ctx[Nn * Cc];       // pooled context
__device__ float g_v[Nn * CBn];        // post-LN/ReLU bottleneck vector

// ---------------------------------------------------------------------------
// K1: logits[n,h,w] = sum_c x[n,c,h,w] * wk_w[c] + wk_b
// block = (n,h) row; 256 threads = 16 w-float4 groups x 16 c-chunks of 32
// ---------------------------------------------------------------------------
__global__ void __launch_bounds__(256, 6)
k_logits(const float* __restrict__ x,
         const float* __restrict__ wk_w,
         const float* __restrict__ wk_b, int n0) {
    int n = n0 + (blockIdx.x >> 6);   // / Hh
    int h = blockIdx.x & 63;          // % Hh
    int tid = threadIdx.x;            // 0..255
    int wq = tid & 15;                // float4 index over w (w = wq*4)
    int cc = tid >> 4;                // c-chunk 0..15 (32 channels each)

    const float4* xp = (const float4*)(x + (((size_t)(n * Cc + cc * 32)) * Hh + h) * Ww) + wq;
    const size_t cstride4 = Sp / 4;   // float4 stride between channels = 1024

    float4 acc = make_float4(0.f, 0.f, 0.f, 0.f);
#pragma unroll 8
    for (int i = 0; i < 32; i++) {
        float wv = __ldg(&wk_w[cc * 32 + i]);
        float4 v = __ldg(xp + (size_t)i * cstride4);
        acc.x += v.x * wv; acc.y += v.y * wv;
        acc.z += v.z * wv; acc.w += v.w * wv;
    }

    __shared__ float sred[16][Ww];
    sred[cc][wq * 4 + 0] = acc.x;
    sred[cc][wq * 4 + 1] = acc.y;
    sred[cc][wq * 4 + 2] = acc.z;
    sred[cc][wq * 4 + 3] = acc.w;
    __syncthreads();

    if (tid < Ww) {
        float s = 0.f;
#pragma unroll
        for (int k = 0; k < 16; k++) s += sred[k][tid];
        g_attn[((size_t)n * Hh + h) * Ww + tid] = s + __ldg(&wk_b[0]);
    }
}

// ---------------------------------------------------------------------------
// K2: softmax over H (axis=1) per (n, w), in place. block per n, 256 threads:
// thread = (w, hq) with 4 h-chunks of 16 cooperating per column.
// ---------------------------------------------------------------------------
__global__ void k_softmax(int n0) {
    int n = n0 + blockIdx.x;
    int tid = threadIdx.x;            // 0..255
    int w = tid & 63;
    int hq = tid >> 6;                // 0..3
    float* L = g_attn + (size_t)n * Sp;

    __shared__ float sp[4][Ww];       // partials
    __shared__ float sfin[Ww];        // combined max / inv-sum

    float vals[16];
    float m = -1e30f;
#pragma unroll
    for (int i = 0; i < 16; i++) {
        vals[i] = L[(hq * 16 + i) * Ww + w];
        m = fmaxf(m, vals[i]);
    }
    sp[hq][w] = m;
    __syncthreads();
    if (hq == 0) sfin[w] = fmaxf(fmaxf(sp[0][w], sp[1][w]), fmaxf(sp[2][w], sp[3][w]));
    __syncthreads();
    float fm = sfin[w];

    float sum = 0.f;
#pragma unroll
    for (int i = 0; i < 16; i++) {
        vals[i] = __expf(vals[i] - fm);
        sum += vals[i];
    }
    sp[hq][w] = sum;
    __syncthreads();
    if (hq == 0) sfin[w] = 1.f / (sp[0][w] + sp[1][w] + sp[2][w] + sp[3][w]);
    __syncthreads();
    float inv = sfin[w];
#pragma unroll
    for (int i = 0; i < 16; i++) L[(hq * 16 + i) * Ww + w] = vals[i] * inv;
}

// ---------------------------------------------------------------------------
// K3: ctx[n,c] = sum_{h,w} x[n,c,h,w] * attn[n,h,w]   (x hits L2)
// block per (n,c); 128 threads reduce 4096 contiguous floats (float4).
// ---------------------------------------------------------------------------
__global__ void k_ctx(const float* __restrict__ x, int n0) {
    int n = n0 + (blockIdx.x >> 9);   // / Cc
    int c = blockIdx.x & 511;         // % Cc
    int tid = threadIdx.x;            // 0..127

    const float4* xp = (const float4*)(x + ((size_t)n * Cc + c) * Sp);
    const float4* ap = (const float4*)(g_attn + (size_t)n * Sp);

    float acc = 0.f;
#pragma unroll
    for (int i = 0; i < 8; i++) {
        float4 xv = __ldg(xp + tid + i * 128);
        float4 av = __ldg(ap + tid + i * 128);
        acc += xv.x * av.x + xv.y * av.y + xv.z * av.z + xv.w * av.w;
    }

    __shared__ float s[128];
    s[tid] = acc;
    __syncthreads();
    if (tid < 64) s[tid] += s[tid + 64];
    __syncthreads();
    if (tid < 32) {
        float v = s[tid] + s[tid + 32];
#pragma unroll
        for (int o = 16; o; o >>= 1) v += __shfl_xor_sync(0xffffffffu, v, o);
        if (tid == 0) g_ctx[(size_t)n * Cc + c] = v;
    }
}

// ---------------------------------------------------------------------------
// K4: bottleneck head: v = ReLU(LN(ctx @ wv1^T)). grid=GRP, 1024 threads:
// warp j (32 warps = 32 bottleneck channels) computes v_j with float4 loads
// of wv1 (4 independent float4 per lane -> fully pipelined 64KB L2 burst).
// ---------------------------------------------------------------------------
__global__ void __launch_bounds__(1024, 1)
k_bneck(const float* __restrict__ wv1,
        const float* __restrict__ ln_g,
        const float* __restrict__ ln_b, int n0) {
    int n = n0 + blockIdx.x;
    int tid = threadIdx.x;            // 0..1023
    int j = tid >> 5;                 // warp = bottleneck channel 0..31
    int lane = tid & 31;

    __shared__ float4 sctx4[Cc / 4];  // 128 float4
    __shared__ float sv[CBn];

    if (tid < Cc / 4)
        sctx4[tid] = __ldg((const float4*)(g_ctx + (size_t)n * Cc) + tid);
    __syncthreads();

    // v_j = dot(ctx, wv1[j,:]) : 128 float4 per row, lane handles 4
    const float4* w1 = (const float4*)(wv1 + (size_t)j * Cc);
    float acc = 0.f;
#pragma unroll
    for (int k = 0; k < 4; k++) {
        int f = lane + k * 32;
        float4 wv = __ldg(w1 + f);
        float4 cx = sctx4[f];
        acc += cx.x * wv.x + cx.y * wv.y + cx.z * wv.z + cx.w * wv.w;
    }
#pragma unroll
    for (int o = 16; o; o >>= 1) acc += __shfl_xor_sync(0xffffffffu, acc, o);
    if (lane == 0) sv[j] = acc;
    __syncthreads();

    // LayerNorm + ReLU over 32 values (warp 0)
    if (tid < 32) {
        float v = sv[lane];
        float mu = v;
#pragma unroll
        for (int o = 16; o; o >>= 1) mu += __shfl_xor_sync(0xffffffffu, mu, o);
        mu *= (1.f / 32.f);
        float d = v - mu;
        float var = d * d;
#pragma unroll
        for (int o = 16; o; o >>= 1) var += __shfl_xor_sync(0xffffffffu, var, o);
        var *= (1.f / 32.f);
        v = d * rsqrtf(var + EPSv) * __ldg(&ln_g[lane]) + __ldg(&ln_b[lane]);
        g_v[(size_t)n * CBn + lane] = fmaxf(v, 0.f);
    }
}

// ---------------------------------------------------------------------------
// K5: out[n,c,:] = x[n,c,:] + dot(v[n,:], wv2[c,:]).  Block per (n,c), 256
// threads x 4 float4. Every thread redundantly computes the 32-FMA delta from
// L2-broadcast v + wv2 rows (256B) -- no sync, no extra hop.
// ---------------------------------------------------------------------------
__global__ void __launch_bounds__(256)
k_add(const float* __restrict__ x, float* __restrict__ out,
      const float* __restrict__ wv2, int n0) {
    int n = n0 + (blockIdx.x >> 9);   // / Cc
    int c = blockIdx.x & 511;         // % Cc
    int tid = threadIdx.x;            // 0..255

    // inline delta: d = dot(v[n,:], wv2[c,:])
    const float4* vp = (const float4*)(g_v + (size_t)n * CBn);
    const float4* w2 = (const float4*)(wv2 + (size_t)c * CBn);
    float d = 0.f;
#pragma unroll
    for (int q = 0; q < CBn / 4; q++) {
        float4 vv = __ldg(vp + q);
        float4 wv = __ldg(w2 + q);
        d += vv.x * wv.x + vv.y * wv.y + vv.z * wv.z + vv.w * wv.w;
    }

    const float4* xp = (const float4*)(x + ((size_t)n * Cc + c) * Sp);
    float4* op = (float4*)(out + ((size_t)n * Cc + c) * Sp);
#pragma unroll
    for (int it = 0; it < 4; it++) {
        int f = it * 256 + tid;       // 1024 float4 per channel
        float4 v = __ldg(xp + f);
        op[f] = make_float4(v.x + d, v.y + d, v.z + d, v.w + d);
    }
}

// ---------------------------------------------------------------------------
extern "C" void kernel_launch(void* const* d_in, const int* in_sizes, int n_in,
                              void* d_out, int out_size) {
    const float* x    = (const float*)d_in[0];
    const float* wk_w = (const float*)d_in[1];
    const float* wk_b = (const float*)d_in[2];
    const float* wv1  = (const float*)d_in[3];
    const float* ln_g = (const float*)d_in[4];
    const float* ln_b = (const float*)d_in[5];
    const float* wv2  = (const float*)d_in[6];
    float* out = (float*)d_out;

    static cudaStream_t streams[NSTREAMS];
    static cudaEvent_t ev_root, ev_done[NSTREAMS];
    static bool res_init = false;
    if (!res_init) {
        for (int i = 0; i < NSTREAMS; i++) {
            cudaStreamCreateWithFlags(&streams[i], cudaStreamNonBlocking);
            cudaEventCreateWithFlags(&ev_done[i], cudaEventDisableTiming);
        }
        cudaEventCreateWithFlags(&ev_root, cudaEventDisableTiming);
        res_init = true;
    }

    // Fork the capture stream into side streams.
    cudaEventRecord(ev_root, 0);
    for (int i = 0; i < NSTREAMS; i++)
        cudaStreamWaitEvent(streams[i], ev_root, 0);

    for (int g = 0; g < Nn / GRP; g++) {
        int n0 = g * GRP;
        cudaStream_t st = streams[g % NSTREAMS];
        k_logits<<<GRP * Hh, 256, 0, st>>>(x, wk_w, wk_b, n0);
        k_softmax<<<GRP, 256, 0, st>>>(n0);
        k_ctx<<<GRP * Cc, 128, 0, st>>>(x, n0);
        k_bneck<<<GRP, 1024, 0, st>>>(wv1, ln_g, ln_b, n0);
        k_add<<<GRP * Cc, 256, 0, st>>>(x, out, wv2, n0);
    }

    for (int i = 0; i < NSTREAMS; i++) {
        cudaEventRecord(ev_done[i], streams[i]);
        cudaStreamWaitEvent(0, ev_done[i], 0);
    }
}

// round 11
// speedup vs baseline: 1.3019x; 1.0247x over previous
#include <cuda_runtime.h>

#define Nn 32
#define Cc 512
#define Hh 64
#define Ww 64
#define CBn 32          // bottleneck channels C/R
#define Sp (Hh*Ww)      // 4096 spatial per channel
#define EPSv 1e-5f
#define GRP 4           // 4 * 8MB = 32MB per group; 3 in flight = 96MB < 126MB L2
#define NSTREAMS 3

// PDL device-side primitives (sm_90+)
__device__ __forceinline__ void pdl_wait() {
    asm volatile("griddepcontrol.wait;" ::: "memory");
}
__device__ __forceinline__ void pdl_trigger() {
    asm volatile("griddepcontrol.launch_dependents;" ::: "memory");
}

// Scratch (allocation-free rule: __device__ globals). Indexed by global n ->
// disjoint across concurrently-running groups.
__device__ float g_attn[Nn * Sp];      // logits -> attn (in place)
__device__ float g_ctx[Nn * Cc];       // pooled context
__device__ float g_v[Nn * CBn];        // post-LN/ReLU bottleneck vector

// ---------------------------------------------------------------------------
// K1: logits[n,h,w] = sum_c x[n,c,h,w] * wk_w[c] + wk_b
// Reads only x/weights (no dependence on prior chain) -> NO pdl_wait: with
// the PDL attr it freely overlaps the previous kernel on its stream.
// ---------------------------------------------------------------------------
__global__ void __launch_bounds__(256, 6)
k_logits(const float* __restrict__ x,
         const float* __restrict__ wk_w,
         const float* __restrict__ wk_b, int n0) {
    int n = n0 + (blockIdx.x >> 6);   // / Hh
    int h = blockIdx.x & 63;          // % Hh
    int tid = threadIdx.x;            // 0..255
    int wq = tid & 15;                // float4 index over w (w = wq*4)
    int cc = tid >> 4;                // c-chunk 0..15 (32 channels each)

    const float4* xp = (const float4*)(x + (((size_t)(n * Cc + cc * 32)) * Hh + h) * Ww) + wq;
    const size_t cstride4 = Sp / 4;   // float4 stride between channels = 1024

    float4 acc = make_float4(0.f, 0.f, 0.f, 0.f);
#pragma unroll 8
    for (int i = 0; i < 32; i++) {
        float wv = __ldg(&wk_w[cc * 32 + i]);
        float4 v = __ldg(xp + (size_t)i * cstride4);
        acc.x += v.x * wv; acc.y += v.y * wv;
        acc.z += v.z * wv; acc.w += v.w * wv;
    }

    __shared__ float sred[16][Ww];
    sred[cc][wq * 4 + 0] = acc.x;
    sred[cc][wq * 4 + 1] = acc.y;
    sred[cc][wq * 4 + 2] = acc.z;
    sred[cc][wq * 4 + 3] = acc.w;
    __syncthreads();

    if (tid < Ww) {
        float s = 0.f;
#pragma unroll
        for (int k = 0; k < 16; k++) s += sred[k][tid];
        g_attn[((size_t)n * Hh + h) * Ww + tid] = s + __ldg(&wk_b[0]);
    }
    __syncthreads();
    pdl_trigger();                    // logits row written -> softmax may go
}

// ---------------------------------------------------------------------------
// K2: softmax over H (axis=1) per (n, w), in place. block per n, 256 threads.
// Fully dependent on logits: wait at top (PDL still hides launch latency).
// ---------------------------------------------------------------------------
__global__ void k_softmax(int n0) {
    pdl_wait();
    int n = n0 + blockIdx.x;
    int tid = threadIdx.x;            // 0..255
    int w = tid & 63;
    int hq = tid >> 6;                // 0..3
    float* L = g_attn + (size_t)n * Sp;

    __shared__ float sp[4][Ww];       // partials
    __shared__ float sfin[Ww];        // combined max / inv-sum

    float vals[16];
    float m = -1e30f;
#pragma unroll
    for (int i = 0; i < 16; i++) {
        vals[i] = L[(hq * 16 + i) * Ww + w];
        m = fmaxf(m, vals[i]);
    }
    sp[hq][w] = m;
    __syncthreads();
    if (hq == 0) sfin[w] = fmaxf(fmaxf(sp[0][w], sp[1][w]), fmaxf(sp[2][w], sp[3][w]));
    __syncthreads();
    float fm = sfin[w];

    float sum = 0.f;
#pragma unroll
    for (int i = 0; i < 16; i++) {
        vals[i] = __expf(vals[i] - fm);
        sum += vals[i];
    }
    sp[hq][w] = sum;
    __syncthreads();
    if (hq == 0) sfin[w] = 1.f / (sp[0][w] + sp[1][w] + sp[2][w] + sp[3][w]);
    __syncthreads();
    float inv = sfin[w];
#pragma unroll
    for (int i = 0; i < 16; i++) L[(hq * 16 + i) * Ww + w] = vals[i] * inv;
    __syncthreads();
    pdl_trigger();                    // attn ready -> ctx may consume
}

// ---------------------------------------------------------------------------
// K3: ctx[n,c] = sum_{h,w} x[n,c,h,w] * attn[n,h,w]   (x hits L2)
// PDL: loads its x tile into registers BEFORE the wait, hiding softmax.
// ---------------------------------------------------------------------------
__global__ void k_ctx(const float* __restrict__ x, int n0) {
    int n = n0 + (blockIdx.x >> 9);   // / Cc
    int c = blockIdx.x & 511;         // % Cc
    int tid = threadIdx.x;            // 0..127

    // Prefetch x tile (independent of softmax)
    const float4* xp = (const float4*)(x + ((size_t)n * Cc + c) * Sp);
    float4 xv[8];
#pragma unroll
    for (int i = 0; i < 8; i++) xv[i] = __ldg(xp + tid + i * 128);

    pdl_wait();                       // attn now valid

    const float4* ap = (const float4*)(g_attn + (size_t)n * Sp);
    float acc = 0.f;
#pragma unroll
    for (int i = 0; i < 8; i++) {
        float4 av = __ldg(ap + tid + i * 128);
        acc += xv[i].x * av.x + xv[i].y * av.y + xv[i].z * av.z + xv[i].w * av.w;
    }

    __shared__ float s[128];
    s[tid] = acc;
    __syncthreads();
    if (tid < 64) s[tid] += s[tid + 64];
    __syncthreads();
    if (tid < 32) {
        float v = s[tid] + s[tid + 32];
#pragma unroll
        for (int o = 16; o; o >>= 1) v += __shfl_xor_sync(0xffffffffu, v, o);
        if (tid == 0) g_ctx[(size_t)n * Cc + c] = v;
    }
    __syncthreads();
    pdl_trigger();                    // this block's ctx written
}

// ---------------------------------------------------------------------------
// K4: bottleneck head: v = ReLU(LN(ctx @ wv1^T)). grid=GRP, 1024 threads.
// PDL: prefetches wv1 into registers BEFORE the wait, hiding ctx's tail.
// ---------------------------------------------------------------------------
__global__ void __launch_bounds__(1024, 1)
k_bneck(const float* __restrict__ wv1,
        const float* __restrict__ ln_g,
        const float* __restrict__ ln_b, int n0) {
    int n = n0 + blockIdx.x;
    int tid = threadIdx.x;            // 0..1023
    int j = tid >> 5;                 // warp = bottleneck channel 0..31
    int lane = tid & 31;

    // Prefetch weights (independent of ctx)
    const float4* w1 = (const float4*)(wv1 + (size_t)j * Cc);
    float4 wv[4];
#pragma unroll
    for (int k = 0; k < 4; k++) wv[k] = __ldg(w1 + lane + k * 32);

    pdl_wait();                       // g_ctx now valid

    __shared__ float4 sctx4[Cc / 4];  // 128 float4
    __shared__ float sv[CBn];
    if (tid < Cc / 4)
        sctx4[tid] = __ldg((const float4*)(g_ctx + (size_t)n * Cc) + tid);
    __syncthreads();

    float acc = 0.f;
#pragma unroll
    for (int k = 0; k < 4; k++) {
        float4 cx = sctx4[lane + k * 32];
        acc += cx.x * wv[k].x + cx.y * wv[k].y + cx.z * wv[k].z + cx.w * wv[k].w;
    }
#pragma unroll
    for (int o = 16; o; o >>= 1) acc += __shfl_xor_sync(0xffffffffu, acc, o);
    if (lane == 0) sv[j] = acc;
    __syncthreads();

    if (tid < 32) {
        float v = sv[lane];
        float mu = v;
#pragma unroll
        for (int o = 16; o; o >>= 1) mu += __shfl_xor_sync(0xffffffffu, mu, o);
        mu *= (1.f / 32.f);
        float d = v - mu;
        float var = d * d;
#pragma unroll
        for (int o = 16; o; o >>= 1) var += __shfl_xor_sync(0xffffffffu, var, o);
        var *= (1.f / 32.f);
        v = d * rsqrtf(var + EPSv) * __ldg(&ln_g[lane]) + __ldg(&ln_b[lane]);
        g_v[(size_t)n * CBn + lane] = fmaxf(v, 0.f);
    }
    __syncthreads();
    pdl_trigger();                    // v ready -> add may consume
}

// ---------------------------------------------------------------------------
// K5: out[n,c,:] = x[n,c,:] + dot(v[n,:], wv2[c,:]).  Block per (n,c).
// PDL: prefetches x + wv2 row BEFORE the wait, hiding bneck entirely.
// ---------------------------------------------------------------------------
__global__ void __launch_bounds__(256)
k_add(const float* __restrict__ x, float* __restrict__ out,
      const float* __restrict__ wv2, int n0) {
    int n = n0 + (blockIdx.x >> 9);   // / Cc
    int c = blockIdx.x & 511;         // % Cc
    int tid = threadIdx.x;            // 0..255

    // Prefetch x (independent of bneck)
    const float4* xp = (const float4*)(x + ((size_t)n * Cc + c) * Sp);
    float4 xv[4];
#pragma unroll
    for (int it = 0; it < 4; it++) xv[it] = __ldg(xp + it * 256 + tid);
    // Prefetch wv2 row (independent of bneck)
    const float4* w2 = (const float4*)(wv2 + (size_t)c * CBn);
    float4 w2v[8];
#pragma unroll
    for (int q = 0; q < 8; q++) w2v[q] = __ldg(w2 + q);

    pdl_wait();                       // g_v now valid

    const float4* vp = (const float4*)(g_v + (size_t)n * CBn);
    float d = 0.f;
#pragma unroll
    for (int q = 0; q < 8; q++) {
        float4 vv = __ldg(vp + q);
        d += vv.x * w2v[q].x + vv.y * w2v[q].y + vv.z * w2v[q].z + vv.w * w2v[q].w;
    }

    float4* op = (float4*)(out + ((size_t)n * Cc + c) * Sp);
#pragma unroll
    for (int it = 0; it < 4; it++) {
        int f = it * 256 + tid;       // 1024 float4 per channel
        op[f] = make_float4(xv[it].x + d, xv[it].y + d, xv[it].z + d, xv[it].w + d);
    }
    pdl_trigger();                    // let next chain's logits overlap our tail
}

// ---------------------------------------------------------------------------
// PDL launch helper
// ---------------------------------------------------------------------------
template <typename K, typename... Args>
static void launch_pdl(K kern, dim3 grid, dim3 block, cudaStream_t st, Args... args) {
    cudaLaunchConfig_t cfg = {};
    cfg.gridDim = grid;
    cfg.blockDim = block;
    cfg.dynamicSmemBytes = 0;
    cfg.stream = st;
    cudaLaunchAttribute attr[1];
    attr[0].id = cudaLaunchAttributeProgrammaticStreamSerialization;
    attr[0].val.programmaticStreamSerializationAllowed = 1;
    cfg.attrs = attr;
    cfg.numAttrs = 1;
    cudaLaunchKernelEx(&cfg, kern, args...);
}

// ---------------------------------------------------------------------------
extern "C" void kernel_launch(void* const* d_in, const int* in_sizes, int n_in,
                              void* d_out, int out_size) {
    const float* x    = (const float*)d_in[0];
    const float* wk_w = (const float*)d_in[1];
    const float* wk_b = (const float*)d_in[2];
    const float* wv1  = (const float*)d_in[3];
    const float* ln_g = (const float*)d_in[4];
    const float* ln_b = (const float*)d_in[5];
    const float* wv2  = (const float*)d_in[6];
    float* out = (float*)d_out;

    static cudaStream_t streams[NSTREAMS];
    static cudaEvent_t ev_root, ev_done[NSTREAMS];
    static bool res_init = false;
    if (!res_init) {
        for (int i = 0; i < NSTREAMS; i++) {
            cudaStreamCreateWithFlags(&streams[i], cudaStreamNonBlocking);
            cudaEventCreateWithFlags(&ev_done[i], cudaEventDisableTiming);
        }
        cudaEventCreateWithFlags(&ev_root, cudaEventDisableTiming);
        res_init = true;
    }

    // Fork the capture stream into side streams.
    cudaEventRecord(ev_root, 0);
    for (int i = 0; i < NSTREAMS; i++)
        cudaStreamWaitEvent(streams[i], ev_root, 0);

    for (int g = 0; g < Nn / GRP; g++) {
        int n0 = g * GRP;
        cudaStream_t st = streams[g % NSTREAMS];
        launch_pdl(k_logits, dim3(GRP * Hh), dim3(256), st, x, wk_w, wk_b, n0);
        launch_pdl(k_softmax, dim3(GRP), dim3(256), st, n0);
        launch_pdl(k_ctx, dim3(GRP * Cc), dim3(128), st, x, n0);
        launch_pdl(k_bneck, dim3(GRP), dim3(1024), st, wv1, ln_g, ln_b, n0);
        launch_pdl(k_add, dim3(GRP * Cc), dim3(256), st, x, out, wv2, n0);
    }

    for (int i = 0; i < NSTREAMS; i++) {
        cudaEventRecord(ev_done[i], streams[i]);
        cudaStreamWaitEvent(0, ev_done[i], 0);
    }
}